// round 6
// baseline (speedup 1.0000x reference)
#include <cuda_runtime.h>
#include <math.h>
#include <stdint.h>

#define BATCH 8
#define T 2048
#define E 1024
#define H 64
#define M_TOTAL (BATCH * T)   // 16384

// Fragment permutation: groups words by (c mod 4), kc-pairs interleaved, so
// lane (g,t)'s mma fragment words are 16B-contiguous.
//   c = 8*kc + t + 4*b  ->  pos = 16*(kc/2) + 4*t + 2*(kc%2) + b
__host__ __device__ __forceinline__ int P64(int c) {
    return 16 * (c / 16) + 4 * (c & 3) + 2 * ((c >> 3) & 1) + ((c & 7) >> 2);
}

// Scratch (tf32 bit patterns), fragment-permuted layouts.
__device__ uint32_t g_Q[M_TOTAL * H];    // [m][P64(h)], pre-scaled 0.125*log2e
__device__ uint32_t g_K[M_TOTAL * H];    // [m][P64(h)]
__device__ uint32_t g_Vt[BATCH * H * T]; // [b][h][blk*64 + P64(key%64)]
__device__ uint32_t g_Wt[192 * E];       // [n][ (k&~31) + P64(k%32) ]

// ---------------------------------------------------------------------------
// helpers
// ---------------------------------------------------------------------------
__device__ __forceinline__ uint32_t f2tf(float x) {
    uint32_t r;
    asm("cvt.rna.tf32.f32 %0, %1;" : "=r"(r) : "f"(x));
    return r;
}
__device__ __forceinline__ float ex2(float x) {
    float r;
    asm("ex2.approx.f32 %0, %1;" : "=f"(r) : "f"(x));
    return r;
}
__device__ __forceinline__ void mma8(float* c,
                                     uint32_t a0, uint32_t a1, uint32_t a2, uint32_t a3,
                                     uint32_t b0, uint32_t b1) {
    asm("mma.sync.aligned.m16n8k8.row.col.f32.tf32.tf32.f32 "
        "{%0,%1,%2,%3},{%4,%5,%6,%7},{%8,%9},{%0,%1,%2,%3};"
        : "+f"(c[0]), "+f"(c[1]), "+f"(c[2]), "+f"(c[3])
        : "r"(a0), "r"(a1), "r"(a2), "r"(a3), "r"(b0), "r"(b1));
}
__device__ __forceinline__ void cpa16(uint32_t saddr, const void* gptr) {
    asm volatile("cp.async.cg.shared.global [%0], [%1], 16;"
                 :: "r"(saddr), "l"(gptr));
}
#define CP_COMMIT() asm volatile("cp.async.commit_group;")
#define CP_WAIT0()  asm volatile("cp.async.wait_group 0;")

// ---------------------------------------------------------------------------
// W pre-convert: g_Wt[n][(k&~31)+P64(k%32)] = tf32(W{q,k,v}[k][n%64])
// ---------------------------------------------------------------------------
__global__ void cvtW_kernel(const float* __restrict__ Wq,
                            const float* __restrict__ Wk,
                            const float* __restrict__ Wv)
{
    int idx = blockIdx.x * 256 + threadIdx.x;   // 0 .. 49151
    int k  = idx / 48;
    int n  = (idx % 48) * 4;
    const float* src = (n < 64)  ? (Wq + (size_t)k * H + n)
                     : (n < 128) ? (Wk + (size_t)k * H + (n - 64))
                                 : (Wv + (size_t)k * H + (n - 128));
    float4 v = *reinterpret_cast<const float4*>(src);
    size_t kp = (size_t)(k & ~31) + P64(k & 31);
    g_Wt[(size_t)(n + 0) * E + kp] = f2tf(v.x);
    g_Wt[(size_t)(n + 1) * E + kp] = f2tf(v.y);
    g_Wt[(size_t)(n + 2) * E + kp] = f2tf(v.z);
    g_Wt[(size_t)(n + 3) * E + kp] = f2tf(v.w);
}

// ---------------------------------------------------------------------------
// Fused QKV projection, tf32 MMA, cp.async double-buffered.
// CTA 128(M) x 192(N), 256 threads, 8 warps (4M x 2N), warp tile 32x96,
// k-step 32.  W fragments load as LDS.128 (permuted layout, stride 48:
// 48*4 % 128 == 64 -> conflict-free wavefronts).
// ---------------------------------------------------------------------------
#define PXS 36
#define PWS 48
#define PROJ_SMEM_BYTES ((2 * 128 * PXS + 2 * 192 * PWS) * 4)   // 110592

__global__ __launch_bounds__(256, 1) void proj_kernel(const float* __restrict__ X)
{
    extern __shared__ uint32_t psm[];
    float*    Xs = (float*)psm;                  // [2][128*36]
    uint32_t* Ws = psm + 2 * 128 * PXS;          // [2][192*48]
    const uint32_t xs_base = (uint32_t)__cvta_generic_to_shared(Xs);
    const uint32_t ws_base = (uint32_t)__cvta_generic_to_shared(Ws);

    const int m0   = blockIdx.x * 128;
    const int tid  = threadIdx.x;
    const int w    = tid >> 5;
    const int lane = tid & 31;
    const int g    = lane >> 2;
    const int t    = lane & 3;
    const int wm   = (w >> 1) * 32;   // 0,32,64,96
    const int wn   = (w & 1) * 96;    // 0,96

    auto issueTile = [&](int buf, int k0) {
#pragma unroll
        for (int i = 0; i < 4; i++) {            // X: 1024 x 16B
            int idx = tid + i * 256;
            int row = idx >> 3;
            int c4  = (idx & 7) << 2;
            cpa16(xs_base + (uint32_t)(buf * 128 * PXS + row * PXS + c4) * 4,
                  X + (size_t)(m0 + row) * E + k0 + c4);
        }
#pragma unroll
        for (int i = 0; i < 6; i++) {            // Wt: 192 rows x 32 k-words
            int idx = tid + i * 256;             // 0..1535
            int row = idx >> 3;                  // 0..191 (n)
            int c4  = (idx & 7) << 2;            // 0..28
            cpa16(ws_base + (uint32_t)(buf * 192 * PWS + row * PWS + c4) * 4,
                  g_Wt + (size_t)row * E + k0 + c4);
        }
        CP_COMMIT();
    };

    float acc[2][12][4] = {};

    issueTile(0, 0);
    for (int ks = 0; ks < 32; ks++) {
        CP_WAIT0();
        __syncthreads();
        if (ks < 31) issueTile((ks + 1) & 1, (ks + 1) * 32);

        const float*    Xb = Xs + (ks & 1) * 128 * PXS;
        const uint32_t* Wb = Ws + (ks & 1) * 192 * PWS;

#pragma unroll
        for (int kc2 = 0; kc2 < 2; kc2++) {
            // X A-fragments for kc = 2*kc2, 2*kc2+1 (scalar fp32 + cvt)
            uint32_t a[2][2][4];
#pragma unroll
            for (int kcl = 0; kcl < 2; kcl++) {
                int c = (kc2 * 2 + kcl) * 8 + t;
#pragma unroll
                for (int mt = 0; mt < 2; mt++) {
                    int r = wm + mt * 16 + g;
                    a[kcl][mt][0] = f2tf(Xb[r * PXS + c]);
                    a[kcl][mt][1] = f2tf(Xb[(r + 8) * PXS + c]);
                    a[kcl][mt][2] = f2tf(Xb[r * PXS + c + 4]);
                    a[kcl][mt][3] = f2tf(Xb[(r + 8) * PXS + c + 4]);
                }
            }
#pragma unroll
            for (int nt = 0; nt < 12; nt++) {
                uint4 wv = *reinterpret_cast<const uint4*>(
                    &Wb[(wn + nt * 8 + g) * PWS + kc2 * 16 + 4 * t]);
#pragma unroll
                for (int mt = 0; mt < 2; mt++) {
                    mma8(acc[mt][nt], a[0][mt][0], a[0][mt][1], a[0][mt][2], a[0][mt][3],
                         wv.x, wv.y);
                    mma8(acc[mt][nt], a[1][mt][0], a[1][mt][1], a[1][mt][2], a[1][mt][3],
                         wv.z, wv.w);
                }
            }
        }
    }

    // Epilogue: scatter to permuted g_Q / g_K / g_Vt (scalar tf32 stores)
    const float QSCALE = 0.125f * 1.4426950408889634f;
    auto storeQKV = [&](int r, int c, float v) {
        if (c < 64) {
            g_Q[(size_t)r * H + P64(c)] = f2tf(v * QSCALE);
        } else if (c < 128) {
            g_K[(size_t)r * H + P64(c - 64)] = f2tf(v);
        } else {
            int h = c - 128, bb = r / T, tk = r % T;
            g_Vt[((size_t)bb * H + h) * T + (tk & ~63) + P64(tk & 63)] = f2tf(v);
        }
    };
#pragma unroll
    for (int mt = 0; mt < 2; mt++) {
        int r0 = m0 + wm + mt * 16 + g;
#pragma unroll
        for (int nt = 0; nt < 12; nt++) {
            int c = wn + nt * 8 + 2 * t;
            storeQKV(r0,     c,     acc[mt][nt][0]);
            storeQKV(r0,     c + 1, acc[mt][nt][1]);
            storeQKV(r0 + 8, c,     acc[mt][nt][2]);
            storeQKV(r0 + 8, c + 1, acc[mt][nt][3]);
        }
    }
}

// ---------------------------------------------------------------------------
// Flash attention (causal), tf32 MMA, cp.async double-buffered, LDS.128
// fragment loads via permuted K / transposed-permuted V layouts.
// Strides 80 (80*4 % 128 == 64) -> conflict-free LDS.128 wavefronts.
// ---------------------------------------------------------------------------
#define KSS 80
#define VSS 80
#define PSS 68
#define ATTN_SMEM_WORDS (2 * 64 * KSS + 2 * 64 * VSS + 4 * 16 * PSS)  // 24832

__global__ __launch_bounds__(128, 2) void attn_kernel(float* __restrict__ out)
{
    extern __shared__ uint32_t sm[];
    uint32_t* Ks = sm;                         // [2][64 keys x 80]
    uint32_t* Vs = sm + 2 * 64 * KSS;          // [2][64 h    x 80]
    uint32_t* Ps = Vs + 2 * 64 * VSS;          // 4 x 16 x 68
    const uint32_t ks_base = (uint32_t)__cvta_generic_to_shared(Ks);
    const uint32_t vs_base = (uint32_t)__cvta_generic_to_shared(Vs);

    // balanced (b, qt) schedule: CTA i and i+148 share an SM, pair sums equal
    const int cidx = blockIdx.x;
    int s;
    if (cidx < 108)       s = 40 + cidx;
    else if (cidx < 148)  s = cidx - 108;
    else                  s = 403 - cidx;
    const int qt = 31 - (s >> 3);
    const int b  = s & 7;
    const int q0 = qt * 64;

    const int tid  = threadIdx.x;
    const int w    = tid >> 5;
    const int lane = tid & 31;
    const int g    = lane >> 2;
    const int t    = lane & 3;

    const uint32_t* __restrict__ Qg = g_Q + ((size_t)b * T + q0) * H;
    const uint32_t* __restrict__ Kg = g_K + (size_t)b * T * H;
    const uint32_t* __restrict__ Vg = g_Vt + (size_t)b * H * T;
    uint32_t* Pw = Ps + w * 16 * PSS;

    auto issueKV = [&](int buf, int k0) {
#pragma unroll
        for (int i = 0; i < 8; i++) {
            int idx = tid + i * 128;           // 0..1023
            int row = idx >> 4;                // 0..63
            int c   = (idx & 15) << 2;         // 0..60
            cpa16(ks_base + (uint32_t)(buf * 64 * KSS + row * KSS + c) * 4,
                  Kg + (size_t)(k0 + row) * H + c);          // row = key
            cpa16(vs_base + (uint32_t)(buf * 64 * VSS + row * VSS + c) * 4,
                  Vg + (size_t)row * T + k0 + c);            // row = h
        }
        CP_COMMIT();
    };

    issueKV(0, 0);

    // Q A-fragments: 8 x LDG.128 from permuted g_Q, unpack to qa[kc][4]
    uint32_t qa[8][4];
    {
        int r = w * 16 + g;
#pragma unroll
        for (int i = 0; i < 4; i++) {
            uint4 lo = *reinterpret_cast<const uint4*>(
                &Qg[(size_t)r * H + i * 16 + 4 * t]);
            uint4 hi = *reinterpret_cast<const uint4*>(
                &Qg[(size_t)(r + 8) * H + i * 16 + 4 * t]);
            qa[2 * i][0] = lo.x; qa[2 * i][1] = hi.x;
            qa[2 * i][2] = lo.y; qa[2 * i][3] = hi.y;
            qa[2 * i + 1][0] = lo.z; qa[2 * i + 1][1] = hi.z;
            qa[2 * i + 1][2] = lo.w; qa[2 * i + 1][3] = hi.w;
        }
    }

    float l0 = 0.f, l1 = 0.f;
    float accO[8][4] = {};

    for (int kt = 0; kt <= qt; kt++) {
        CP_WAIT0();
        __syncthreads();
        if (kt < qt) issueKV((kt + 1) & 1, (kt + 1) * 64);

        const uint32_t* Kb = Ks + (kt & 1) * 64 * KSS;
        const uint32_t* Vb = Vs + (kt & 1) * 64 * VSS;

        // ---- S = Q @ K^T (log2-domain scores), LDS.128 B-fragments ----
        float sv[8][4] = {};
#pragma unroll
        for (int kc2 = 0; kc2 < 4; kc2++) {
#pragma unroll
            for (int nt = 0; nt < 8; nt++) {
                uint4 kb = *reinterpret_cast<const uint4*>(
                    &Kb[(nt * 8 + g) * KSS + kc2 * 16 + 4 * t]);
                mma8(sv[nt], qa[2*kc2][0], qa[2*kc2][1], qa[2*kc2][2], qa[2*kc2][3],
                     kb.x, kb.y);
                mma8(sv[nt], qa[2*kc2+1][0], qa[2*kc2+1][1], qa[2*kc2+1][2], qa[2*kc2+1][3],
                     kb.z, kb.w);
            }
        }

        // causal mask on the diagonal tile
        if (kt == qt) {
#pragma unroll
            for (int nt = 0; nt < 8; nt++) {
                int cc = nt * 8 + 2 * t;
                int r0 = w * 16 + g;
                int r1 = r0 + 8;
                if (cc     > r0) sv[nt][0] = -1e30f;
                if (cc + 1 > r0) sv[nt][1] = -1e30f;
                if (cc     > r1) sv[nt][2] = -1e30f;
                if (cc + 1 > r1) sv[nt][3] = -1e30f;
            }
        }

        // ---- p = 2^sv; accumulate l; stage P (plain layout) ----
#pragma unroll
        for (int nt = 0; nt < 8; nt++) {
            float p0 = ex2(sv[nt][0]);
            float p1 = ex2(sv[nt][1]);
            float p2 = ex2(sv[nt][2]);
            float p3 = ex2(sv[nt][3]);
            l0 += p0 + p1;
            l1 += p2 + p3;
            *reinterpret_cast<uint2*>(&Pw[g * PSS + nt * 8 + 2 * t]) =
                make_uint2(f2tf(p0), f2tf(p1));
            *reinterpret_cast<uint2*>(&Pw[(g + 8) * PSS + nt * 8 + 2 * t]) =
                make_uint2(f2tf(p2), f2tf(p3));
        }
        __syncwarp();

        // ---- O += P @ V, LDS.128 V-fragments ----
#pragma unroll
        for (int kc2 = 0; kc2 < 4; kc2++) {
            uint32_t ap[2][4];
#pragma unroll
            for (int kcl = 0; kcl < 2; kcl++) {
                int c = (kc2 * 2 + kcl) * 8 + t;
                ap[kcl][0] = Pw[g * PSS + c];
                ap[kcl][1] = Pw[(g + 8) * PSS + c];
                ap[kcl][2] = Pw[g * PSS + c + 4];
                ap[kcl][3] = Pw[(g + 8) * PSS + c + 4];
            }
#pragma unroll
            for (int nt = 0; nt < 8; nt++) {
                uint4 vb = *reinterpret_cast<const uint4*>(
                    &Vb[(nt * 8 + g) * VSS + kc2 * 16 + 4 * t]);
                mma8(accO[nt], ap[0][0], ap[0][1], ap[0][2], ap[0][3], vb.x, vb.y);
                mma8(accO[nt], ap[1][0], ap[1][1], ap[1][2], ap[1][3], vb.z, vb.w);
            }
        }
    }

    // epilogue: reduce l across the quad, normalize, store
    l0 += __shfl_xor_sync(0xffffffffu, l0, 1);
    l0 += __shfl_xor_sync(0xffffffffu, l0, 2);
    l1 += __shfl_xor_sync(0xffffffffu, l1, 1);
    l1 += __shfl_xor_sync(0xffffffffu, l1, 2);
    float i0 = 1.f / l0, i1 = 1.f / l1;
#pragma unroll
    for (int nt = 0; nt < 8; nt++) {
        int r = q0 + w * 16 + g;
        int c = nt * 8 + 2 * t;
        float* o = out + ((size_t)b * T + r) * H + c;
        *reinterpret_cast<float2*>(o) =
            make_float2(accO[nt][0] * i0, accO[nt][1] * i0);
        *reinterpret_cast<float2*>(o + 8 * H) =
            make_float2(accO[nt][2] * i1, accO[nt][3] * i1);
    }
}

// ---------------------------------------------------------------------------
extern "C" void kernel_launch(void* const* d_in, const int* in_sizes, int n_in,
                              void* d_out, int out_size)
{
    const float* X  = (const float*)d_in[0];
    const float* Wq = (const float*)d_in[1];
    const float* Wk = (const float*)d_in[2];
    const float* Wv = (const float*)d_in[3];
    float* out = (float*)d_out;

    // 0) W -> tf32 transposed+permuted layout
    cvtW_kernel<<<192, 256>>>(Wq, Wk, Wv);

    // 1) Fused QKV projection
    cudaFuncSetAttribute(proj_kernel,
                         cudaFuncAttributeMaxDynamicSharedMemorySize,
                         PROJ_SMEM_BYTES);
    proj_kernel<<<M_TOTAL / 128, 256, PROJ_SMEM_BYTES>>>(X);

    // 2) Causal flash attention
    const size_t smem_bytes = (size_t)ATTN_SMEM_WORDS * 4;   // 99328
    cudaFuncSetAttribute(attn_kernel,
                         cudaFuncAttributeMaxDynamicSharedMemorySize,
                         (int)smem_bytes);
    attn_kernel<<<(T / 64) * BATCH, 128, smem_bytes>>>(out);
}

// round 7
// speedup vs baseline: 1.5714x; 1.5714x over previous
#include <cuda_runtime.h>
#include <cuda_fp16.h>
#include <math.h>
#include <stdint.h>

#define BATCH 8
#define T 2048
#define E 1024
#define H 64
#define M_TOTAL (BATCH * T)   // 16384

// Scratch (fp16). Static device arrays: allocation-guard safe.
__device__ __half g_Q[M_TOTAL * H];     // [m][h], pre-scaled 0.125*log2e
__device__ __half g_K[M_TOTAL * H];     // [m][h]
__device__ __half g_Vt[BATCH * H * T];  // [b][h][t]  (transposed)
__device__ __half g_Wt[192 * E];        // [n][k]     (Wq|Wk|Wv transposed)

// ---------------------------------------------------------------------------
// helpers
// ---------------------------------------------------------------------------
__device__ __forceinline__ float ex2(float x) {
    float r;
    asm("ex2.approx.f32 %0, %1;" : "=f"(r) : "f"(x));
    return r;
}
__device__ __forceinline__ uint32_t pack2h(float lo, float hi) {
    __half2 h = __floats2half2_rn(lo, hi);   // .x = lo (low 16 bits)
    return *reinterpret_cast<uint32_t*>(&h);
}
// D(16x8,f32) += A(16x16,f16,row) * B(16x8,f16,col)
__device__ __forceinline__ void mma16(float* c,
                                      uint32_t a0, uint32_t a1, uint32_t a2, uint32_t a3,
                                      uint32_t b0, uint32_t b1) {
    asm("mma.sync.aligned.m16n8k16.row.col.f32.f16.f16.f32 "
        "{%0,%1,%2,%3},{%4,%5,%6,%7},{%8,%9},{%0,%1,%2,%3};"
        : "+f"(c[0]), "+f"(c[1]), "+f"(c[2]), "+f"(c[3])
        : "r"(a0), "r"(a1), "r"(a2), "r"(a3), "r"(b0), "r"(b1));
}
__device__ __forceinline__ void cpa16(uint32_t saddr, const void* gptr) {
    asm volatile("cp.async.cg.shared.global [%0], [%1], 16;"
                 :: "r"(saddr), "l"(gptr));
}
#define CP_COMMIT() asm volatile("cp.async.commit_group;")
#define CP_WAIT0()  asm volatile("cp.async.wait_group 0;")

// ---------------------------------------------------------------------------
// W pre-convert: g_Wt[n][k] = fp16(W{q,k,v}[k][n%64]), n-major (transposed)
// ---------------------------------------------------------------------------
__global__ void cvtW_kernel(const float* __restrict__ Wq,
                            const float* __restrict__ Wk,
                            const float* __restrict__ Wv)
{
    int idx = blockIdx.x * 256 + threadIdx.x;   // 0 .. 49151
    int n   = idx >> 8;                          // 0..191
    int k4  = (idx & 255) * 4;                   // 0..1020
    const float* src = (n < 64)  ? (Wq + n)
                     : (n < 128) ? (Wk + (n - 64))
                                 : (Wv + (n - 128));
    __half h[4];
#pragma unroll
    for (int j = 0; j < 4; j++)
        h[j] = __float2half_rn(src[(size_t)(k4 + j) * H]);
    *reinterpret_cast<uint2*>(&g_Wt[(size_t)n * E + k4]) =
        *reinterpret_cast<uint2*>(h);
}

// ---------------------------------------------------------------------------
// Fused QKV projection, fp16 MMA (m16n8k16), cp.async double-buffered.
// CTA 128(M) x 192(N), 256 threads, 8 warps (4M x 2N), warp tile 32x96,
// k-step 32 (2 mma-k).  Xs fp32 stride 40 (float2 frag loads conflict-free),
// Ws fp16 stride 40 (scalar 4B frag loads conflict-free).
// ---------------------------------------------------------------------------
#define PXS 40
#define PWSH 40
#define PROJ_SMEM_BYTES (2 * 128 * PXS * 4 + 2 * 192 * PWSH * 2)   // 71680

__global__ __launch_bounds__(256, 1) void proj_kernel(const float* __restrict__ X)
{
    extern __shared__ uint32_t psm[];
    float*  Xs = (float*)psm;                       // [2][128*40] fp32
    __half* Ws = (__half*)(psm + 2 * 128 * PXS);    // [2][192*40] fp16
    const uint32_t xs_base = (uint32_t)__cvta_generic_to_shared(Xs);
    const uint32_t ws_base = (uint32_t)__cvta_generic_to_shared(Ws);

    const int m0   = blockIdx.x * 128;
    const int tid  = threadIdx.x;
    const int w    = tid >> 5;
    const int lane = tid & 31;
    const int g    = lane >> 2;
    const int t    = lane & 3;
    const int wm   = (w >> 1) * 32;   // 0,32,64,96
    const int wn   = (w & 1) * 96;    // 0,96

    auto issueTile = [&](int buf, int k0) {
#pragma unroll
        for (int i = 0; i < 4; i++) {            // X: 1024 x 16B
            int idx = tid + i * 256;
            int row = idx >> 3;                  // 0..127
            int c4  = (idx & 7) << 2;            // 0..28
            cpa16(xs_base + (uint32_t)(buf * 128 * PXS + row * PXS + c4) * 4,
                  X + (size_t)(m0 + row) * E + k0 + c4);
        }
#pragma unroll
        for (int i = 0; i < 3; i++) {            // W: 192 rows x 32 fp16 = 768 x 16B
            int idx = tid + i * 256;
            int row = idx >> 2;                  // 0..191
            int c8  = (idx & 3) << 3;            // 0,8,16,24
            cpa16(ws_base + (uint32_t)(buf * 192 * PWSH + row * PWSH + c8) * 2,
                  g_Wt + (size_t)row * E + k0 + c8);
        }
        CP_COMMIT();
    };

    float acc[2][12][4] = {};

    issueTile(0, 0);
    for (int ks = 0; ks < 32; ks++) {
        CP_WAIT0();
        __syncthreads();
        if (ks < 31) issueTile((ks + 1) & 1, (ks + 1) * 32);

        const float*  Xb = Xs + (ks & 1) * 128 * PXS;
        const __half* Wb = Ws + (ks & 1) * 192 * PWSH;

#pragma unroll
        for (int kc = 0; kc < 2; kc++) {
            // A fragments: fp32 float2 loads + cvt-pack to fp16x2
            uint32_t a[2][4];
#pragma unroll
            for (int mt = 0; mt < 2; mt++) {
                int r = wm + mt * 16 + g;
                int c = kc * 16 + 2 * t;
                float2 x0 = *reinterpret_cast<const float2*>(&Xb[r * PXS + c]);
                float2 x1 = *reinterpret_cast<const float2*>(&Xb[(r + 8) * PXS + c]);
                float2 x2 = *reinterpret_cast<const float2*>(&Xb[r * PXS + c + 8]);
                float2 x3 = *reinterpret_cast<const float2*>(&Xb[(r + 8) * PXS + c + 8]);
                a[mt][0] = pack2h(x0.x, x0.y);
                a[mt][1] = pack2h(x1.x, x1.y);
                a[mt][2] = pack2h(x2.x, x2.y);
                a[mt][3] = pack2h(x3.x, x3.y);
            }
#pragma unroll
            for (int nt = 0; nt < 12; nt++) {
                int n = wn + nt * 8 + g;
                uint32_t b0 = *reinterpret_cast<const uint32_t*>(
                    &Wb[n * PWSH + kc * 16 + 2 * t]);
                uint32_t b1 = *reinterpret_cast<const uint32_t*>(
                    &Wb[n * PWSH + kc * 16 + 2 * t + 8]);
                mma16(acc[0][nt], a[0][0], a[0][1], a[0][2], a[0][3], b0, b1);
                mma16(acc[1][nt], a[1][0], a[1][1], a[1][2], a[1][3], b0, b1);
            }
        }
    }

    // Epilogue: fp16 stores (Q pre-scaled by 0.125*log2e; V transposed)
    const float QSCALE = 0.125f * 1.4426950408889634f;
#pragma unroll
    for (int mt = 0; mt < 2; mt++) {
        int r0 = m0 + wm + mt * 16 + g;
#pragma unroll
        for (int nt = 0; nt < 12; nt++) {
            int c = wn + nt * 8 + 2 * t;
            if (c < 64) {
                *reinterpret_cast<uint32_t*>(&g_Q[(size_t)r0 * H + c]) =
                    pack2h(acc[mt][nt][0] * QSCALE, acc[mt][nt][1] * QSCALE);
                *reinterpret_cast<uint32_t*>(&g_Q[(size_t)(r0 + 8) * H + c]) =
                    pack2h(acc[mt][nt][2] * QSCALE, acc[mt][nt][3] * QSCALE);
            } else if (c < 128) {
                int cc = c - 64;
                *reinterpret_cast<uint32_t*>(&g_K[(size_t)r0 * H + cc]) =
                    pack2h(acc[mt][nt][0], acc[mt][nt][1]);
                *reinterpret_cast<uint32_t*>(&g_K[(size_t)(r0 + 8) * H + cc]) =
                    pack2h(acc[mt][nt][2], acc[mt][nt][3]);
            } else {
                int h = c - 128;
                int bb = r0 / T, tk = r0 % T;
                __half* vb = g_Vt + (size_t)bb * H * T;
                vb[(size_t)h * T + tk]           = __float2half_rn(acc[mt][nt][0]);
                vb[(size_t)(h + 1) * T + tk]     = __float2half_rn(acc[mt][nt][1]);
                vb[(size_t)h * T + tk + 8]       = __float2half_rn(acc[mt][nt][2]);
                vb[(size_t)(h + 1) * T + tk + 8] = __float2half_rn(acc[mt][nt][3]);
            }
        }
    }
}

// ---------------------------------------------------------------------------
// Flash attention (causal), fp16 MMA (m16n8k16), cp.async double-buffered.
// 4 warps; warp w owns q rows w*16..+15; key tile 64; no-max exp2 softmax.
// Ks [key][h] / Vs [h][key] / Pw [q][key], all fp16 stride 72 (= 36 words:
// 36g+t mod 32 = 4g+t -> conflict-free scalar 4B fragment loads).
// smem 45 KB -> 3 CTAs/SM.
// ---------------------------------------------------------------------------
#define KSH 72
#define ATTN_SMEM_BYTES ((2 * 64 * KSH + 2 * 64 * KSH + 4 * 16 * KSH) * 2)  // 46080

__global__ __launch_bounds__(128, 3) void attn_kernel(float* __restrict__ out)
{
    extern __shared__ __half hsm[];
    __half* Ks = hsm;                          // [2][64 keys x 72]
    __half* Vs = Ks + 2 * 64 * KSH;            // [2][64 h    x 72]
    __half* Ps = Vs + 2 * 64 * KSH;            // 4 warps x 16 q x 72
    const uint32_t ks_base = (uint32_t)__cvta_generic_to_shared(Ks);
    const uint32_t vs_base = (uint32_t)__cvta_generic_to_shared(Vs);

    // balanced (b, qt) schedule: CTA i and i+148 share an SM, pair sums equal
    const int cidx = blockIdx.x;
    int s;
    if (cidx < 108)       s = 40 + cidx;
    else if (cidx < 148)  s = cidx - 108;
    else                  s = 403 - cidx;
    const int qt = 31 - (s >> 3);
    const int b  = s & 7;
    const int q0 = qt * 64;

    const int tid  = threadIdx.x;
    const int w    = tid >> 5;
    const int lane = tid & 31;
    const int g    = lane >> 2;
    const int t    = lane & 3;

    const __half* __restrict__ Qg = g_Q + ((size_t)b * T + q0) * H;
    const __half* __restrict__ Kg = g_K + (size_t)b * T * H;
    const __half* __restrict__ Vg = g_Vt + (size_t)b * H * T;
    __half* Pw = Ps + w * 16 * KSH;

    auto issueKV = [&](int buf, int k0) {
#pragma unroll
        for (int i = 0; i < 4; i++) {
            int idx = tid + i * 128;           // 0..511
            int row = idx >> 3;                // 0..63
            int c8  = (idx & 7) << 3;          // 0..56
            cpa16(ks_base + (uint32_t)(buf * 64 * KSH + row * KSH + c8) * 2,
                  Kg + (size_t)(k0 + row) * H + c8);         // row = key
            cpa16(vs_base + (uint32_t)(buf * 64 * KSH + row * KSH + c8) * 2,
                  Vg + (size_t)row * T + k0 + c8);           // row = h
        }
        CP_COMMIT();
    };

    issueKV(0, 0);

    // Q A-fragments from gmem (fp16 pairs)
    uint32_t qa[4][4];
    {
        int r = w * 16 + g;
#pragma unroll
        for (int kc = 0; kc < 4; kc++) {
            int c = kc * 16 + 2 * t;
            qa[kc][0] = *reinterpret_cast<const uint32_t*>(&Qg[(size_t)r * H + c]);
            qa[kc][1] = *reinterpret_cast<const uint32_t*>(&Qg[(size_t)(r + 8) * H + c]);
            qa[kc][2] = *reinterpret_cast<const uint32_t*>(&Qg[(size_t)r * H + c + 8]);
            qa[kc][3] = *reinterpret_cast<const uint32_t*>(&Qg[(size_t)(r + 8) * H + c + 8]);
        }
    }

    float l0 = 0.f, l1 = 0.f;
    float accO[8][4] = {};

    for (int kt = 0; kt <= qt; kt++) {
        CP_WAIT0();
        __syncthreads();
        if (kt < qt) issueKV((kt + 1) & 1, (kt + 1) * 64);

        const __half* Kb = Ks + (kt & 1) * 64 * KSH;
        const __half* Vb = Vs + (kt & 1) * 64 * KSH;

        // ---- S = Q @ K^T (log2-domain scores) ----
        float sv[8][4] = {};
#pragma unroll
        for (int kc = 0; kc < 4; kc++) {
#pragma unroll
            for (int nt = 0; nt < 8; nt++) {
                int key = nt * 8 + g;
                uint32_t b0 = *reinterpret_cast<const uint32_t*>(
                    &Kb[key * KSH + kc * 16 + 2 * t]);
                uint32_t b1 = *reinterpret_cast<const uint32_t*>(
                    &Kb[key * KSH + kc * 16 + 2 * t + 8]);
                mma16(sv[nt], qa[kc][0], qa[kc][1], qa[kc][2], qa[kc][3], b0, b1);
            }
        }

        // causal mask on the diagonal tile
        if (kt == qt) {
#pragma unroll
            for (int nt = 0; nt < 8; nt++) {
                int cc = nt * 8 + 2 * t;
                int r0 = w * 16 + g;
                int r1 = r0 + 8;
                if (cc     > r0) sv[nt][0] = -1e30f;
                if (cc + 1 > r0) sv[nt][1] = -1e30f;
                if (cc     > r1) sv[nt][2] = -1e30f;
                if (cc + 1 > r1) sv[nt][3] = -1e30f;
            }
        }

        // ---- p = 2^sv (no max, no rescale); accumulate l; stage P fp16 ----
#pragma unroll
        for (int nt = 0; nt < 8; nt++) {
            float p0 = ex2(sv[nt][0]);
            float p1 = ex2(sv[nt][1]);
            float p2 = ex2(sv[nt][2]);
            float p3 = ex2(sv[nt][3]);
            l0 += p0 + p1;
            l1 += p2 + p3;
            *reinterpret_cast<uint32_t*>(&Pw[g * KSH + nt * 8 + 2 * t]) =
                pack2h(p0, p1);
            *reinterpret_cast<uint32_t*>(&Pw[(g + 8) * KSH + nt * 8 + 2 * t]) =
                pack2h(p2, p3);
        }
        __syncwarp();

        // ---- O += P @ V ----
#pragma unroll
        for (int kc = 0; kc < 4; kc++) {
            int c = kc * 16 + 2 * t;
            uint32_t a0 = *reinterpret_cast<const uint32_t*>(&Pw[g * KSH + c]);
            uint32_t a1 = *reinterpret_cast<const uint32_t*>(&Pw[(g + 8) * KSH + c]);
            uint32_t a2 = *reinterpret_cast<const uint32_t*>(&Pw[g * KSH + c + 8]);
            uint32_t a3 = *reinterpret_cast<const uint32_t*>(&Pw[(g + 8) * KSH + c + 8]);
#pragma unroll
            for (int nt = 0; nt < 8; nt++) {
                int h = nt * 8 + g;
                uint32_t b0 = *reinterpret_cast<const uint32_t*>(
                    &Vb[h * KSH + kc * 16 + 2 * t]);
                uint32_t b1 = *reinterpret_cast<const uint32_t*>(
                    &Vb[h * KSH + kc * 16 + 2 * t + 8]);
                mma16(accO[nt], a0, a1, a2, a3, b0, b1);
            }
        }
    }

    // epilogue: reduce l across the quad, normalize, store
    l0 += __shfl_xor_sync(0xffffffffu, l0, 1);
    l0 += __shfl_xor_sync(0xffffffffu, l0, 2);
    l1 += __shfl_xor_sync(0xffffffffu, l1, 1);
    l1 += __shfl_xor_sync(0xffffffffu, l1, 2);
    float i0 = 1.f / l0, i1 = 1.f / l1;
#pragma unroll
    for (int nt = 0; nt < 8; nt++) {
        int r = q0 + w * 16 + g;
        int c = nt * 8 + 2 * t;
        float* o = out + ((size_t)b * T + r) * H + c;
        *reinterpret_cast<float2*>(o) =
            make_float2(accO[nt][0] * i0, accO[nt][1] * i0);
        *reinterpret_cast<float2*>(o + 8 * H) =
            make_float2(accO[nt][2] * i1, accO[nt][3] * i1);
    }
}

// ---------------------------------------------------------------------------
extern "C" void kernel_launch(void* const* d_in, const int* in_sizes, int n_in,
                              void* d_out, int out_size)
{
    const float* X  = (const float*)d_in[0];
    const float* Wq = (const float*)d_in[1];
    const float* Wk = (const float*)d_in[2];
    const float* Wv = (const float*)d_in[3];
    float* out = (float*)d_out;

    // 0) W -> fp16 transposed layout
    cvtW_kernel<<<192, 256>>>(Wq, Wk, Wv);

    // 1) Fused QKV projection
    cudaFuncSetAttribute(proj_kernel,
                         cudaFuncAttributeMaxDynamicSharedMemorySize,
                         PROJ_SMEM_BYTES);
    proj_kernel<<<M_TOTAL / 128, 256, PROJ_SMEM_BYTES>>>(X);

    // 2) Causal flash attention
    cudaFuncSetAttribute(attn_kernel,
                         cudaFuncAttributeMaxDynamicSharedMemorySize,
                         ATTN_SMEM_BYTES);
    attn_kernel<<<(T / 64) * BATCH, 128, ATTN_SMEM_BYTES>>>(out);
}

// round 8
// speedup vs baseline: 1.6304x; 1.0375x over previous
#include <cuda_runtime.h>
#include <cuda_fp16.h>
#include <math.h>
#include <stdint.h>

#define BATCH 8
#define T 2048
#define E 1024
#define H 64
#define M_TOTAL (BATCH * T)   // 16384

// Scratch (fp16). Static device arrays: allocation-guard safe.
__device__ __half g_Q[M_TOTAL * H];     // [m][h], pre-scaled 0.125*log2e
__device__ __half g_K[M_TOTAL * H];     // [m][h]
__device__ __half g_Vt[BATCH * H * T];  // [b][h][t]  (transposed)
__device__ __half g_Wt[192 * E];        // [n][k]     (Wq|Wk|Wv transposed)

// ---------------------------------------------------------------------------
// helpers
// ---------------------------------------------------------------------------
__device__ __forceinline__ float ex2(float x) {
    float r;
    asm("ex2.approx.f32 %0, %1;" : "=f"(r) : "f"(x));
    return r;
}
__device__ __forceinline__ uint32_t pack2h(float lo, float hi) {
    __half2 h = __floats2half2_rn(lo, hi);
    return *reinterpret_cast<uint32_t*>(&h);
}
__device__ __forceinline__ void mma16(float* c,
                                      uint32_t a0, uint32_t a1, uint32_t a2, uint32_t a3,
                                      uint32_t b0, uint32_t b1) {
    asm("mma.sync.aligned.m16n8k16.row.col.f32.f16.f16.f32 "
        "{%0,%1,%2,%3},{%4,%5,%6,%7},{%8,%9},{%0,%1,%2,%3};"
        : "+f"(c[0]), "+f"(c[1]), "+f"(c[2]), "+f"(c[3])
        : "r"(a0), "r"(a1), "r"(a2), "r"(a3), "r"(b0), "r"(b1));
}
__device__ __forceinline__ void ldm_x4(uint32_t& r0, uint32_t& r1,
                                       uint32_t& r2, uint32_t& r3, uint32_t a) {
    asm volatile("ldmatrix.sync.aligned.m8n8.x4.shared.b16 {%0,%1,%2,%3}, [%4];"
                 : "=r"(r0), "=r"(r1), "=r"(r2), "=r"(r3) : "r"(a));
}
__device__ __forceinline__ void stm_x4(uint32_t a, uint32_t r0, uint32_t r1,
                                       uint32_t r2, uint32_t r3) {
    asm volatile("stmatrix.sync.aligned.m8n8.x4.shared.b16 [%0], {%1,%2,%3,%4};"
                 :: "r"(a), "r"(r0), "r"(r1), "r"(r2), "r"(r3));
}
__device__ __forceinline__ void cpa16(uint32_t saddr, const void* gptr) {
    asm volatile("cp.async.cg.shared.global [%0], [%1], 16;"
                 :: "r"(saddr), "l"(gptr));
}
#define CP_COMMIT() asm volatile("cp.async.commit_group;")
#define CP_WAIT0()  asm volatile("cp.async.wait_group 0;")

// ---------------------------------------------------------------------------
// W pre-convert, coalesced 64x64 tile transpose via smem.
// grid (16 k-tiles, 3 matrices), 256 threads.
// ---------------------------------------------------------------------------
__global__ void cvtW_kernel(const float* __restrict__ Wq,
                            const float* __restrict__ Wk,
                            const float* __restrict__ Wv)
{
    __shared__ __half ts[64][72];   // [n][k], padded
    const int k0 = blockIdx.x * 64;
    const int n0 = blockIdx.y * 64;
    const float* __restrict__ src =
        (blockIdx.y == 0) ? Wq : (blockIdx.y == 1) ? Wk : Wv;
    const int tid = threadIdx.x;

#pragma unroll
    for (int i = 0; i < 4; i++) {            // coalesced read [k][n]
        int idx  = tid + i * 256;            // 0..1023
        int krow = idx >> 4;                 // 0..63
        int c4   = (idx & 15) << 2;          // 0..60
        float4 v = *reinterpret_cast<const float4*>(
            src + (size_t)(k0 + krow) * H + c4);
        ts[c4 + 0][krow] = __float2half_rn(v.x);
        ts[c4 + 1][krow] = __float2half_rn(v.y);
        ts[c4 + 2][krow] = __float2half_rn(v.z);
        ts[c4 + 3][krow] = __float2half_rn(v.w);
    }
    __syncthreads();
#pragma unroll
    for (int i = 0; i < 4; i++) {            // coalesced write [n][k]
        int odx = tid + i * 256;
        int n   = odx >> 4;                  // 0..63
        int k4  = (odx & 15) << 2;           // 0..60
        *reinterpret_cast<uint2*>(&g_Wt[(size_t)(n0 + n) * E + k0 + k4]) =
            *reinterpret_cast<const uint2*>(&ts[n][k4]);
    }
}

// ---------------------------------------------------------------------------
// Fused QKV projection, fp16 MMA, X staged as fp16 (reg double buffer),
// W via cp.async.  CTA 128(M) x 192(N), 8 warps as 2M x 4N (warp 64m x 48n).
// Strides 40 halfs (20 words: 20g mod 32 distinct) -> conflict-free frags.
// ---------------------------------------------------------------------------
#define XSH 40
#define WSH 40
#define PROJ_SMEM_BYTES ((2 * 128 * XSH + 2 * 192 * WSH) * 2)   // 51200

__global__ __launch_bounds__(256, 1) void proj_kernel(const float* __restrict__ X)
{
    extern __shared__ __half psm[];
    __half* Xs = psm;                        // [2][128*40]
    __half* Ws = psm + 2 * 128 * XSH;        // [2][192*40]
    const uint32_t ws_base = (uint32_t)__cvta_generic_to_shared(Ws);

    const int m0   = blockIdx.x * 128;
    const int tid  = threadIdx.x;
    const int w    = tid >> 5;
    const int lane = tid & 31;
    const int g    = lane >> 2;
    const int t    = lane & 3;
    const int wm   = (w >> 2) * 64;          // 0,64
    const int wn   = (w & 3) * 48;           // 0,48,96,144

    float4 xa[4];
    auto loadX = [&](int k0) {
#pragma unroll
        for (int i = 0; i < 4; i++) {
            int idx = tid + i * 256;         // 0..1023
            int row = idx >> 3;              // 0..127
            int c4  = (idx & 7) << 2;        // 0..28
            xa[i] = *reinterpret_cast<const float4*>(
                X + (size_t)(m0 + row) * E + k0 + c4);
        }
    };
    auto storeX = [&](int buf) {
#pragma unroll
        for (int i = 0; i < 4; i++) {
            int idx = tid + i * 256;
            int row = idx >> 3;
            int c4  = (idx & 7) << 2;
            *reinterpret_cast<uint2*>(&Xs[buf * 128 * XSH + row * XSH + c4]) =
                make_uint2(pack2h(xa[i].x, xa[i].y), pack2h(xa[i].z, xa[i].w));
        }
    };
    auto issueW = [&](int buf, int k0) {
#pragma unroll
        for (int i = 0; i < 3; i++) {        // 192 x 32 halfs = 768 x 16B
            int idx = tid + i * 256;
            int n   = idx >> 2;              // 0..191
            int c8  = (idx & 3) << 3;        // 0,8,16,24
            cpa16(ws_base + (uint32_t)(buf * 192 * WSH + n * WSH + c8) * 2,
                  g_Wt + (size_t)n * E + k0 + c8);
        }
        CP_COMMIT();
    };

    float acc[4][6][4] = {};

    loadX(0);
    issueW(0, 0);
    for (int ks = 0; ks < 32; ks++) {
        storeX(ks & 1);
        CP_WAIT0();
        __syncthreads();
        if (ks < 31) { loadX((ks + 1) * 32); issueW((ks + 1) & 1, (ks + 1) * 32); }

        const __half* Xb = Xs + (ks & 1) * 128 * XSH;
        const __half* Wb = Ws + (ks & 1) * 192 * WSH;

#pragma unroll
        for (int kc = 0; kc < 2; kc++) {
            uint32_t a[4][4];
#pragma unroll
            for (int mt = 0; mt < 4; mt++) {
                int r = wm + mt * 16 + g;
                int c = kc * 16 + 2 * t;
                a[mt][0] = *reinterpret_cast<const uint32_t*>(&Xb[r * XSH + c]);
                a[mt][1] = *reinterpret_cast<const uint32_t*>(&Xb[(r + 8) * XSH + c]);
                a[mt][2] = *reinterpret_cast<const uint32_t*>(&Xb[r * XSH + c + 8]);
                a[mt][3] = *reinterpret_cast<const uint32_t*>(&Xb[(r + 8) * XSH + c + 8]);
            }
#pragma unroll
            for (int nt = 0; nt < 6; nt++) {
                int n = wn + nt * 8 + g;
                uint32_t b0 = *reinterpret_cast<const uint32_t*>(
                    &Wb[n * WSH + kc * 16 + 2 * t]);
                uint32_t b1 = *reinterpret_cast<const uint32_t*>(
                    &Wb[n * WSH + kc * 16 + 2 * t + 8]);
#pragma unroll
                for (int mt = 0; mt < 4; mt++)
                    mma16(acc[mt][nt], a[mt][0], a[mt][1], a[mt][2], a[mt][3], b0, b1);
            }
        }
    }

    // Epilogue: fp16 stores (Q pre-scaled; V transposed)
    const float QSCALE = 0.125f * 1.4426950408889634f;
#pragma unroll
    for (int mt = 0; mt < 4; mt++) {
        int r0 = m0 + wm + mt * 16 + g;
#pragma unroll
        for (int nt = 0; nt < 6; nt++) {
            int c = wn + nt * 8 + 2 * t;
            if (c < 64) {
                *reinterpret_cast<uint32_t*>(&g_Q[(size_t)r0 * H + c]) =
                    pack2h(acc[mt][nt][0] * QSCALE, acc[mt][nt][1] * QSCALE);
                *reinterpret_cast<uint32_t*>(&g_Q[(size_t)(r0 + 8) * H + c]) =
                    pack2h(acc[mt][nt][2] * QSCALE, acc[mt][nt][3] * QSCALE);
            } else if (c < 128) {
                int cc = c - 64;
                *reinterpret_cast<uint32_t*>(&g_K[(size_t)r0 * H + cc]) =
                    pack2h(acc[mt][nt][0], acc[mt][nt][1]);
                *reinterpret_cast<uint32_t*>(&g_K[(size_t)(r0 + 8) * H + cc]) =
                    pack2h(acc[mt][nt][2], acc[mt][nt][3]);
            } else {
                int h = c - 128;
                int bb = r0 / T, tk = r0 % T;
                __half* vb = g_Vt + (size_t)bb * H * T;
                vb[(size_t)h * T + tk]           = __float2half_rn(acc[mt][nt][0]);
                vb[(size_t)(h + 1) * T + tk]     = __float2half_rn(acc[mt][nt][1]);
                vb[(size_t)h * T + tk + 8]       = __float2half_rn(acc[mt][nt][2]);
                vb[(size_t)(h + 1) * T + tk + 8] = __float2half_rn(acc[mt][nt][3]);
            }
        }
    }
}

// ---------------------------------------------------------------------------
// Flash attention (causal), fp16 MMA, 2x2 warp split:
// warp (qw,kw) handles 32 q rows x 32 keys -> K/V fragment bytes halved.
// ldmatrix/stmatrix fragment movement; partial O/l reduced across kw pairs.
// K/V stride 72 halfs, P stride 40 halfs (both conflict-free).
// ---------------------------------------------------------------------------
#define KSH 72
#define PSH 40
#define ATTN_SMEM_BYTES ((2 * 64 * KSH * 2 + 4 * 32 * PSH) * 2)   // 47104

__global__ __launch_bounds__(128, 2) void attn_kernel(float* __restrict__ out)
{
    extern __shared__ __half hsm[];
    __half* Ks = hsm;                          // [2][64 keys x 72]
    __half* Vs = Ks + 2 * 64 * KSH;            // [2][64 h    x 72]
    __half* Ps = Vs + 2 * 64 * KSH;            // 4 warps x 32q x 40
    const uint32_t ks_base = (uint32_t)__cvta_generic_to_shared(Ks);
    const uint32_t vs_base = (uint32_t)__cvta_generic_to_shared(Vs);
    const uint32_t ps_base = (uint32_t)__cvta_generic_to_shared(Ps);

    // balanced (b, qt) schedule: CTA i and i+148 share an SM, pair sums equal
    const int cidx = blockIdx.x;
    int s;
    if (cidx < 108)       s = 40 + cidx;
    else if (cidx < 148)  s = cidx - 108;
    else                  s = 403 - cidx;
    const int qt = 31 - (s >> 3);
    const int b  = s & 7;
    const int q0 = qt * 64;

    const int tid  = threadIdx.x;
    const int w    = tid >> 5;
    const int lane = tid & 31;
    const int g    = lane >> 2;
    const int t    = lane & 3;
    const int qw   = w >> 1;     // 0: q 0-31, 1: q 32-63
    const int kw   = w & 1;      // 0: keys 0-31, 1: keys 32-63
    const int lr   = lane & 7;   // ldmatrix row-in-tile
    const int lt   = lane >> 3;  // ldmatrix tile id (0..3)

    const __half* __restrict__ Qg = g_Q + ((size_t)b * T + q0) * H;
    const __half* __restrict__ Kg = g_K + (size_t)b * T * H;
    const __half* __restrict__ Vg = g_Vt + (size_t)b * H * T;
    const uint32_t pw_base = ps_base + (uint32_t)(w * 32 * PSH) * 2;

    auto issueKV = [&](int buf, int k0) {
#pragma unroll
        for (int i = 0; i < 4; i++) {
            int idx = tid + i * 128;           // 0..511
            int row = idx >> 3;                // 0..63
            int c8  = (idx & 7) << 3;          // 0..56
            cpa16(ks_base + (uint32_t)(buf * 64 * KSH + row * KSH + c8) * 2,
                  Kg + (size_t)(k0 + row) * H + c8);         // row = key
            cpa16(vs_base + (uint32_t)(buf * 64 * KSH + row * KSH + c8) * 2,
                  Vg + (size_t)row * T + k0 + c8);           // row = h
        }
        CP_COMMIT();
    };

    issueKV(0, 0);

    // Q A-fragments: qa[qh][kc][4] for q rows qw*32 + qh*16 + {g, g+8}
    uint32_t qa[2][4][4];
#pragma unroll
    for (int qh = 0; qh < 2; qh++) {
        int r = qw * 32 + qh * 16 + g;
#pragma unroll
        for (int kc = 0; kc < 4; kc++) {
            int c = kc * 16 + 2 * t;
            qa[qh][kc][0] = *reinterpret_cast<const uint32_t*>(&Qg[(size_t)r * H + c]);
            qa[qh][kc][1] = *reinterpret_cast<const uint32_t*>(&Qg[(size_t)(r + 8) * H + c]);
            qa[qh][kc][2] = *reinterpret_cast<const uint32_t*>(&Qg[(size_t)r * H + c + 8]);
            qa[qh][kc][3] = *reinterpret_cast<const uint32_t*>(&Qg[(size_t)(r + 8) * H + c + 8]);
        }
    }

    float lacc[2][2] = {};         // [qh][row-half]
    float accO[2][8][4] = {};      // [qh][nh][4]

    for (int kt = 0; kt <= qt; kt++) {
        CP_WAIT0();
        __syncthreads();
        if (kt < qt) issueKV((kt + 1) & 1, (kt + 1) * 64);

        const uint32_t kbuf = (uint32_t)((kt & 1) * 64 * KSH) * 2;
        const bool diag = (kt == qt);

        // warp (qw=0, kw=1) is fully masked on the diagonal tile
        if (!(diag && qw == 0 && kw == 1)) {
            // ---- S = Q @ K^T ----
            float sv[2][4][4] = {};
#pragma unroll
            for (int hc = 0; hc < 2; hc++) {
#pragma unroll
                for (int nt = 0; nt < 4; nt++) {
                    uint32_t kb0, kb1, kb2, kb3;
                    uint32_t ka = ks_base + kbuf +
                        (uint32_t)((kw * 32 + nt * 8 + lr) * KSH + hc * 32 + lt * 8) * 2;
                    ldm_x4(kb0, kb1, kb2, kb3, ka);
#pragma unroll
                    for (int qh = 0; qh < 2; qh++) {
                        mma16(sv[qh][nt], qa[qh][2*hc][0], qa[qh][2*hc][1],
                              qa[qh][2*hc][2], qa[qh][2*hc][3], kb0, kb1);
                        mma16(sv[qh][nt], qa[qh][2*hc+1][0], qa[qh][2*hc+1][1],
                              qa[qh][2*hc+1][2], qa[qh][2*hc+1][3], kb2, kb3);
                    }
                }
            }

            // causal mask on the diagonal tile
            if (diag) {
#pragma unroll
                for (int qh = 0; qh < 2; qh++) {
                    int r0 = qw * 32 + qh * 16 + g;
                    int r1 = r0 + 8;
#pragma unroll
                    for (int nt = 0; nt < 4; nt++) {
                        int cc = kw * 32 + nt * 8 + 2 * t;
                        if (cc     > r0) sv[qh][nt][0] = -1e30f;
                        if (cc + 1 > r0) sv[qh][nt][1] = -1e30f;
                        if (cc     > r1) sv[qh][nt][2] = -1e30f;
                        if (cc + 1 > r1) sv[qh][nt][3] = -1e30f;
                    }
                }
            }

            // ---- p = 2^sv; accumulate l; stmatrix P ----
#pragma unroll
            for (int qh = 0; qh < 2; qh++) {
                uint32_t pr0[4], pr1[4];
#pragma unroll
                for (int nt = 0; nt < 4; nt++) {
                    float p0 = ex2(sv[qh][nt][0]);
                    float p1 = ex2(sv[qh][nt][1]);
                    float p2 = ex2(sv[qh][nt][2]);
                    float p3 = ex2(sv[qh][nt][3]);
                    lacc[qh][0] += p0 + p1;
                    lacc[qh][1] += p2 + p3;
                    pr0[nt] = pack2h(p0, p1);
                    pr1[nt] = pack2h(p2, p3);
                }
                stm_x4(pw_base + (uint32_t)((qh * 16 + lr) * PSH + lt * 8) * 2,
                       pr0[0], pr0[1], pr0[2], pr0[3]);
                stm_x4(pw_base + (uint32_t)((qh * 16 + 8 + lr) * PSH + lt * 8) * 2,
                       pr1[0], pr1[1], pr1[2], pr1[3]);
            }
            __syncwarp();

            // ---- O += P @ V ----
            uint32_t pa[2][2][4];
#pragma unroll
            for (int qh = 0; qh < 2; qh++)
#pragma unroll
                for (int kc = 0; kc < 2; kc++) {
                    uint32_t paddr = pw_base + (uint32_t)(
                        (qh * 16 + ((lane >> 3) & 1) * 8 + lr) * PSH +
                        kc * 16 + (lane >> 4) * 8) * 2;
                    ldm_x4(pa[qh][kc][0], pa[qh][kc][1], pa[qh][kc][2], pa[qh][kc][3],
                           paddr);
                }
#pragma unroll
            for (int nh = 0; nh < 8; nh++) {
                uint32_t vb0, vb1, vb2, vb3;
                uint32_t va = vs_base + kbuf +
                    (uint32_t)((nh * 8 + lr) * KSH + kw * 32 + lt * 8) * 2;
                ldm_x4(vb0, vb1, vb2, vb3, va);
#pragma unroll
                for (int qh = 0; qh < 2; qh++) {
                    mma16(accO[qh][nh], pa[qh][0][0], pa[qh][0][1],
                          pa[qh][0][2], pa[qh][0][3], vb0, vb1);
                    mma16(accO[qh][nh], pa[qh][1][0], pa[qh][1][1],
                          pa[qh][1][2], pa[qh][1][3], vb2, vb3);
                }
            }
        }
    }

    // ---- epilogue: reduce partials across the kw pair, normalize, store ----
#pragma unroll
    for (int qh = 0; qh < 2; qh++)
#pragma unroll
        for (int i = 0; i < 2; i++) {
            lacc[qh][i] += __shfl_xor_sync(0xffffffffu, lacc[qh][i], 1);
            lacc[qh][i] += __shfl_xor_sync(0xffffffffu, lacc[qh][i], 2);
        }

    __syncthreads();   // all tiles done; K/V smem reusable as f32 staging
    float* Ored = (float*)hsm;                       // [2 qw][32 q][64 h]
    float* Lred = (float*)(Vs);                      // [2 qw][32 q]

    if (kw == 1) {
#pragma unroll
        for (int qh = 0; qh < 2; qh++) {
            int r = qw * 32 + qh * 16 + g;
#pragma unroll
            for (int nh = 0; nh < 8; nh++) {
                int c = nh * 8 + 2 * t;
                *reinterpret_cast<float2*>(&Ored[(size_t)r * 64 + c]) =
                    make_float2(accO[qh][nh][0], accO[qh][nh][1]);
                *reinterpret_cast<float2*>(&Ored[(size_t)(r + 8) * 64 + c]) =
                    make_float2(accO[qh][nh][2], accO[qh][nh][3]);
            }
            if (t == 0) {
                Lred[r]     = lacc[qh][0];
                Lred[r + 8] = lacc[qh][1];
            }
        }
    }
    __syncthreads();

    if (kw == 0) {
#pragma unroll
        for (int qh = 0; qh < 2; qh++) {
            int rl = qw * 32 + qh * 16 + g;
            float i0 = 1.f / (lacc[qh][0] + Lred[rl]);
            float i1 = 1.f / (lacc[qh][1] + Lred[rl + 8]);
            int r = q0 + rl;
#pragma unroll
            for (int nh = 0; nh < 8; nh++) {
                int c = nh * 8 + 2 * t;
                float2 o0 = *reinterpret_cast<const float2*>(&Ored[(size_t)rl * 64 + c]);
                float2 o1 = *reinterpret_cast<const float2*>(&Ored[(size_t)(rl + 8) * 64 + c]);
                float* o = out + ((size_t)b * T + r) * H + c;
                *reinterpret_cast<float2*>(o) =
                    make_float2((accO[qh][nh][0] + o0.x) * i0,
                                (accO[qh][nh][1] + o0.y) * i0);
                *reinterpret_cast<float2*>(o + 8 * H) =
                    make_float2((accO[qh][nh][2] + o1.x) * i1,
                                (accO[qh][nh][3] + o1.y) * i1);
            }
        }
    }
}

// ---------------------------------------------------------------------------
extern "C" void kernel_launch(void* const* d_in, const int* in_sizes, int n_in,
                              void* d_out, int out_size)
{
    const float* X  = (const float*)d_in[0];
    const float* Wq = (const float*)d_in[1];
    const float* Wk = (const float*)d_in[2];
    const float* Wv = (const float*)d_in[3];
    float* out = (float*)d_out;

    // 0) W -> fp16 transposed layout (coalesced tile transpose)
    cvtW_kernel<<<dim3(16, 3), 256>>>(Wq, Wk, Wv);

    // 1) Fused QKV projection
    cudaFuncSetAttribute(proj_kernel,
                         cudaFuncAttributeMaxDynamicSharedMemorySize,
                         PROJ_SMEM_BYTES);
    proj_kernel<<<M_TOTAL / 128, 256, PROJ_SMEM_BYTES>>>(X);

    // 2) Causal flash attention
    cudaFuncSetAttribute(attn_kernel,
                         cudaFuncAttributeMaxDynamicSharedMemorySize,
                         ATTN_SMEM_BYTES);
    attn_kernel<<<(T / 64) * BATCH, 128, ATTN_SMEM_BYTES>>>(out);
}